// round 6
// baseline (speedup 1.0000x reference)
#include <cuda_runtime.h>
#include <math.h>

#define XD 128
#define NDEPTH 222
#define MPAD 120
// max_extent = sqrt(3*(64^2)) * 1.5
static constexpr double MAX_EXTENT_D = 166.27687752661222232;
static constexpr double DT_D         = 2.0 * MAX_EXTENT_D / (NDEPTH - 1);
static constexpr double SCALE_D      = 2.0 * MAX_EXTENT_D / NDEPTH;

__device__ __forceinline__ void slab_axis(float r, float b, float& tlo, float& thi, bool& empty) {
    if (fabsf(r) > 1e-12f) {
        float inv = __frcp_rn(r);
        float ta = (-1.0f - b) * inv;
        float tb = (128.0f - b) * inv;
        tlo = fmaxf(tlo, fminf(ta, tb));
        thi = fminf(thi, fmaxf(ta, tb));
    } else if (b <= -1.0f || b >= 128.0f) {
        empty = true;
    }
}

__global__ void __launch_bounds__(128, 8)
projector_kernel(const float* __restrict__ vol,
                 const float* __restrict__ vec,
                 float* __restrict__ out) {
    const int tid = threadIdx.x;
    const int j   = blockIdx.x;
    const int n   = blockIdx.y;
    const int h   = blockIdx.z;          // depth half (steps m with m%2 == h)

    const float* V = vec + n * 12;
    const float rx = __ldg(V + 0), ry = __ldg(V + 1), rz = __ldg(V + 2);
    const float dx = __ldg(V + 3), dy = __ldg(V + 4), dz = __ldg(V + 5);
    const float ux = __ldg(V + 6), uy = __ldg(V + 7), uz = __ldg(V + 8);
    const float vx = __ldg(V + 9), vy = __ldg(V + 10), vz = __ldg(V + 11);

    const float t0 = (float)(-MAX_EXTENT_D);
    const float dt = (float)DT_D;
    const float jc = (float)j - 63.5f;

    __shared__ int4   As[MPAD];    // byte offsets of the 4 rows (this half's steps)
    __shared__ float4 Ws[MPAD];    // bilinear weights
    __shared__ float  Red[4][132]; // padded reduce buffer

    // Fast path: z-axis-aligned geometry -> per-block-uniform (x,y) sample,
    // z index is EXACTLY the pixel k with fz = 0 (single z-tap, weight 1).
    const bool fast = (rz == 0.0f) & (uz == 0.0f) & (dz == 0.0f) &
                      (vx == 0.0f) & (vy == 0.0f) & (vz == 1.0f);

    if (fast) {
        const int w    = tid >> 5;   // warp id (0..3)
        const int lane = tid & 31;   // covers z = 4*lane .. 4*lane+3

        const float bx = fmaf(jc, ux, dx) + 63.5f;
        const float by = fmaf(jc, uy, dy) + 63.5f;

        float tlo = -3.0e38f, thi = 3.0e38f;
        bool empty = false;
        slab_axis(rx, bx, tlo, thi, empty);
        slab_axis(ry, by, tlo, thi, empty);

        int i0 = 0, cnt = 0;
        if (!empty && thi >= tlo) {
            i0 = max(0, (int)ceilf((tlo - t0) / dt) - 1);
            int i1 = min(NDEPTH - 1, (int)floorf((thi - t0) / dt) + 1);
            cnt = i1 - i0 + 1;
            if (cnt < 0) cnt = 0;
        }
        // This half handles steps m = h, h+2, ... -> M of them.
        const int M    = (cnt + 1 - h) > 0 ? (cnt + 1 - h) >> 1 : 0;
        const int sPad = (M + 7) & ~7;     // pad to unroll granularity (zero-weight tail)

        // Metadata phase: one pass (sPad <= 112 < 128 threads).
        if (tid < sPad) {
            const int s = tid;
            if (s < M) {
                const int m = h + 2 * s;
                const float t  = fmaf((float)(i0 + m), dt, t0);
                const float px = fmaf(t, rx, bx);
                const float py = fmaf(t, ry, by);
                const float x0f = floorf(px);
                const float y0f = floorf(py);
                const float fx = px - x0f;
                const float fy = py - y0f;
                const int x0 = (int)x0f;
                const int y0 = (int)y0f;
                const float wx0 = ((unsigned)x0       < (unsigned)XD) ? (1.0f - fx) : 0.0f;
                const float wx1 = ((unsigned)(x0 + 1) < (unsigned)XD) ? fx          : 0.0f;
                const float wy0 = ((unsigned)y0       < (unsigned)XD) ? (1.0f - fy) : 0.0f;
                const float wy1 = ((unsigned)(y0 + 1) < (unsigned)XD) ? fy          : 0.0f;
                const int xc0 = min(max(x0, 0), XD - 1);
                const int xc1 = min(max(x0 + 1, 0), XD - 1);
                const int yc0 = min(max(y0, 0), XD - 1);
                const int yc1 = min(max(y0 + 1, 0), XD - 1);
                As[s] = make_int4(((xc0 * XD + yc0) * XD) * 4, ((xc0 * XD + yc1) * XD) * 4,
                                  ((xc1 * XD + yc0) * XD) * 4, ((xc1 * XD + yc1) * XD) * 4);
                Ws[s] = make_float4(wx0 * wy0, wx0 * wy1, wx1 * wy0, wx1 * wy1);
            } else {
                As[s] = make_int4(0, 0, 0, 0);
                Ws[s] = make_float4(0.0f, 0.0f, 0.0f, 0.0f);
            }
        }
        __syncthreads();

        // Mainloop: 2 steps per trip -> 8 x LDG.128 in flight + 32 FFMA.
        const char* volb = (const char*)vol + (lane << 4);
        float4 S = make_float4(0.0f, 0.0f, 0.0f, 0.0f);
        for (int s = 2 * w; s < sPad; s += 8) {
            const int4   A0 = As[s];
            const int4   A1 = As[s + 1];
            const float4 W0 = Ws[s];
            const float4 W1 = Ws[s + 1];
            const float4 r0 = __ldg((const float4*)(volb + A0.x));
            const float4 r1 = __ldg((const float4*)(volb + A0.y));
            const float4 r2 = __ldg((const float4*)(volb + A0.z));
            const float4 r3 = __ldg((const float4*)(volb + A0.w));
            const float4 r4 = __ldg((const float4*)(volb + A1.x));
            const float4 r5 = __ldg((const float4*)(volb + A1.y));
            const float4 r6 = __ldg((const float4*)(volb + A1.z));
            const float4 r7 = __ldg((const float4*)(volb + A1.w));
            S.x = fmaf(W0.x, r0.x, S.x); S.y = fmaf(W0.x, r0.y, S.y);
            S.z = fmaf(W0.x, r0.z, S.z); S.w = fmaf(W0.x, r0.w, S.w);
            S.x = fmaf(W0.y, r1.x, S.x); S.y = fmaf(W0.y, r1.y, S.y);
            S.z = fmaf(W0.y, r1.z, S.z); S.w = fmaf(W0.y, r1.w, S.w);
            S.x = fmaf(W0.z, r2.x, S.x); S.y = fmaf(W0.z, r2.y, S.y);
            S.z = fmaf(W0.z, r2.z, S.z); S.w = fmaf(W0.z, r2.w, S.w);
            S.x = fmaf(W0.w, r3.x, S.x); S.y = fmaf(W0.w, r3.y, S.y);
            S.z = fmaf(W0.w, r3.z, S.z); S.w = fmaf(W0.w, r3.w, S.w);
            S.x = fmaf(W1.x, r4.x, S.x); S.y = fmaf(W1.x, r4.y, S.y);
            S.z = fmaf(W1.x, r4.z, S.z); S.w = fmaf(W1.x, r4.w, S.w);
            S.x = fmaf(W1.y, r5.x, S.x); S.y = fmaf(W1.y, r5.y, S.y);
            S.z = fmaf(W1.y, r5.z, S.z); S.w = fmaf(W1.y, r5.w, S.w);
            S.x = fmaf(W1.z, r6.x, S.x); S.y = fmaf(W1.z, r6.y, S.y);
            S.z = fmaf(W1.z, r6.z, S.z); S.w = fmaf(W1.z, r6.w, S.w);
            S.x = fmaf(W1.w, r7.x, S.x); S.y = fmaf(W1.w, r7.y, S.y);
            S.z = fmaf(W1.w, r7.z, S.z); S.w = fmaf(W1.w, r7.w, S.w);
        }
        Red[w][lane * 4 + 0] = S.x;
        Red[w][lane * 4 + 1] = S.y;
        Red[w][lane * 4 + 2] = S.z;
        Red[w][lane * 4 + 3] = S.w;
        __syncthreads();

        // Combine the two depth-halves with exactly 2 deterministic atomic adds.
        const float acc = Red[0][tid] + Red[1][tid] + Red[2][tid] + Red[3][tid];
        atomicAdd(out + ((n * XD) + j) * XD + tid, acc * (float)SCALE_D);
    } else {
        // General path: per-pixel trilinear gather. Only half 0 does the work
        // (full depth); half 1 exits. Output written with a plain store over
        // the zeroed buffer.
        if (h != 0) return;
        const int z = tid;
        const float kc = (float)z - 63.5f;
        const float bx = fmaf(kc, vx, fmaf(jc, ux, dx)) + 63.5f;
        const float by = fmaf(kc, vy, fmaf(jc, uy, dy)) + 63.5f;
        const float bz = fmaf(kc, vz, fmaf(jc, uz, dz)) + 63.5f;

        float tlo = -3.0e38f, thi = 3.0e38f;
        bool empty = false;
        slab_axis(rx, bx, tlo, thi, empty);
        slab_axis(ry, by, tlo, thi, empty);
        slab_axis(rz, bz, tlo, thi, empty);

        int i0 = 0, i1 = -1;
        if (!empty && thi >= tlo) {
            i0 = max(0, (int)ceilf((tlo - t0) / dt) - 1);
            i1 = min(NDEPTH - 1, (int)floorf((thi - t0) / dt) + 1);
        }

        float sum = 0.0f;
        for (int i = i0; i <= i1; ++i) {
            const float t  = fmaf((float)i, dt, t0);
            const float px = fmaf(t, rx, bx);
            const float py = fmaf(t, ry, by);
            const float pz = fmaf(t, rz, bz);

            const float x0f = floorf(px);
            const float y0f = floorf(py);
            const float z0f = floorf(pz);
            const float fx = px - x0f;
            const float fy = py - y0f;
            const float fz = pz - z0f;
            const int x0 = (int)x0f;
            const int y0 = (int)y0f;
            const int z0 = (int)z0f;

            const int a = x0 * (XD * XD) + y0 * XD + z0;

            const bool xv0 = ((unsigned)x0 < (unsigned)XD);
            const bool xv1 = ((unsigned)(x0 + 1) < (unsigned)XD);
            const bool yv0 = ((unsigned)y0 < (unsigned)XD);
            const bool yv1 = ((unsigned)(y0 + 1) < (unsigned)XD);
            const bool zv0 = ((unsigned)z0 < (unsigned)XD);
            const bool zv1 = ((unsigned)(z0 + 1) < (unsigned)XD);

            const float v000 = (xv0 & yv0 & zv0) ? __ldg(vol + a)                    : 0.0f;
            const float v001 = (xv0 & yv0 & zv1) ? __ldg(vol + a + 1)                : 0.0f;
            const float v010 = (xv0 & yv1 & zv0) ? __ldg(vol + a + XD)               : 0.0f;
            const float v011 = (xv0 & yv1 & zv1) ? __ldg(vol + a + XD + 1)           : 0.0f;
            const float v100 = (xv1 & yv0 & zv0) ? __ldg(vol + a + XD * XD)          : 0.0f;
            const float v101 = (xv1 & yv0 & zv1) ? __ldg(vol + a + XD * XD + 1)      : 0.0f;
            const float v110 = (xv1 & yv1 & zv0) ? __ldg(vol + a + XD * XD + XD)     : 0.0f;
            const float v111 = (xv1 & yv1 & zv1) ? __ldg(vol + a + XD * XD + XD + 1) : 0.0f;

            const float c00 = fmaf(fz, v001 - v000, v000);
            const float c01 = fmaf(fz, v011 - v010, v010);
            const float c10 = fmaf(fz, v101 - v100, v100);
            const float c11 = fmaf(fz, v111 - v110, v110);
            const float c0  = fmaf(fy, c01 - c00, c00);
            const float c1  = fmaf(fy, c11 - c10, c10);
            sum += fmaf(fx, c1 - c0, c0);
        }
        out[((n * XD) + j) * XD + z] = sum * (float)SCALE_D;
    }
}

extern "C" void kernel_launch(void* const* d_in, const int* in_sizes, int n_in,
                              void* d_out, int out_size) {
    const float* vol = (const float*)d_in[0];
    const float* vec = (const float*)d_in[1];
    float* out = (float*)d_out;

    const int N = in_sizes[1] / 12;
    cudaMemsetAsync(out, 0, (size_t)out_size * sizeof(float));
    dim3 grid(XD, N, 2);
    dim3 block(128);
    projector_kernel<<<grid, block>>>(vol, vec, out);
}

// round 7
// speedup vs baseline: 1.1915x; 1.1915x over previous
#include <cuda_runtime.h>
#include <math.h>

#define XD 128
#define NDEPTH 222
#define EMAX 928
// max_extent = sqrt(3*(64^2)) * 1.5
static constexpr double MAX_EXTENT_D = 166.27687752661222232;
static constexpr double DT_D         = 2.0 * MAX_EXTENT_D / (NDEPTH - 1);
static constexpr double SCALE_D      = 2.0 * MAX_EXTENT_D / NDEPTH;

__device__ __forceinline__ void slab_axis(float r, float b, float& tlo, float& thi, bool& empty) {
    if (fabsf(r) > 1e-12f) {
        float inv = __frcp_rn(r);
        float ta = (-1.0f - b) * inv;
        float tb = (128.0f - b) * inv;
        tlo = fmaxf(tlo, fminf(ta, tb));
        thi = fminf(thi, fmaxf(ta, tb));
    } else if (b <= -1.0f || b >= 128.0f) {
        empty = true;
    }
}

// Patch of step i: integer base cell (x0,y0) and the 4 boundary-zeroed weights.
__device__ __forceinline__ void patchOf(int i, float bx, float by, float rx, float ry,
                                        int& x0, int& y0,
                                        float& wx0, float& wx1, float& wy0, float& wy1) {
    const float t  = fmaf((float)i, (float)DT_D, (float)(-MAX_EXTENT_D));
    const float px = fmaf(t, rx, bx);
    const float py = fmaf(t, ry, by);
    const float xf = floorf(px), yf = floorf(py);
    x0 = (int)xf; y0 = (int)yf;
    const float fx = px - xf, fy = py - yf;
    wx0 = ((unsigned)x0       < (unsigned)XD) ? 1.0f - fx : 0.0f;
    wx1 = ((unsigned)(x0 + 1) < (unsigned)XD) ? fx        : 0.0f;
    wy0 = ((unsigned)y0       < (unsigned)XD) ? 1.0f - fy : 0.0f;
    wy1 = ((unsigned)(y0 + 1) < (unsigned)XD) ? fy        : 0.0f;
}

__device__ __forceinline__ int warpInclScan(int x) {
    #pragma unroll
    for (int d = 1; d < 32; d <<= 1) {
        int y = __shfl_up_sync(0xffffffffu, x, d);
        if ((threadIdx.x & 31) >= d) x += y;
    }
    return x;
}

__global__ void __launch_bounds__(128, 8)
projector_kernel(const float* __restrict__ vol,
                 const float* __restrict__ vec,
                 float* __restrict__ out) {
    const int tid = threadIdx.x;
    const int j   = blockIdx.x;
    const int n   = blockIdx.y;

    const float* V = vec + n * 12;
    const float rx = __ldg(V + 0), ry = __ldg(V + 1), rz = __ldg(V + 2);
    const float dx = __ldg(V + 3), dy = __ldg(V + 4), dz = __ldg(V + 5);
    const float ux = __ldg(V + 6), uy = __ldg(V + 7), uz = __ldg(V + 8);
    const float vx = __ldg(V + 9), vy = __ldg(V + 10), vz = __ldg(V + 11);

    const float t0 = (float)(-MAX_EXTENT_D);
    const float dt = (float)DT_D;
    const float jc = (float)j - 63.5f;

    __shared__ int2  AW[EMAX];     // compacted (row byte offset, weight bits)
    __shared__ float Red[4][132];  // padded reduce buffer
    __shared__ int   wsum[8];

    // Fast path: z-axis-aligned geometry -> per-block-uniform (x,y) sample,
    // z index is EXACTLY the pixel k with fz = 0 (single z-tap, weight 1).
    // Extra guard: major-axis step > 1 voxel so each cell appears in at most
    // 2 consecutive step patches (required by the dedup ownership rule).
    const bool fast = (rz == 0.0f) & (uz == 0.0f) & (dz == 0.0f) &
                      (vx == 0.0f) & (vy == 0.0f) & (vz == 1.0f) &
                      (fmaxf(fabsf(rx), fabsf(ry)) * dt > 1.02f);

    if (fast) {
        const int w    = tid >> 5;
        const int lane = tid & 31;

        const float bx = fmaf(jc, ux, dx) + 63.5f;
        const float by = fmaf(jc, uy, dy) + 63.5f;

        float tlo = -3.0e38f, thi = 3.0e38f;
        bool empty = false;
        slab_axis(rx, bx, tlo, thi, empty);
        slab_axis(ry, by, tlo, thi, empty);

        int i0 = 0, cnt = 0;
        if (!empty && thi >= tlo) {
            i0 = max(0, (int)ceilf((tlo - t0) / dt) - 1);
            int i1 = min(NDEPTH - 1, (int)floorf((thi - t0) / dt) + 1);
            cnt = i1 - i0 + 1;
            if (cnt < 0) cnt = 0;
        }

        // ---- Phase 1: per-step owned-entry count (steps s=tid and s=tid+128) ----
        int c0 = 0, c1 = 0;
        #pragma unroll
        for (int p = 0; p < 2; ++p) {
            const int s = tid + p * 128;
            int c = 0;
            if (s < cnt) {
                int x0, y0; float wx0, wx1, wy0, wy1;
                patchOf(i0 + s, bx, by, rx, ry, x0, y0, wx0, wx1, wy0, wy1);
                int xp = 0x40000000, yp = 0x40000000;
                if (s > 0) {
                    float d0, d1, d2, d3;
                    patchOf(i0 + s - 1, bx, by, rx, ry, xp, yp, d0, d1, d2, d3);
                }
                #pragma unroll
                for (int a = 0; a < 2; ++a)
                    #pragma unroll
                    for (int b = 0; b < 2; ++b) {
                        const unsigned dxp = (unsigned)(x0 + a - xp);
                        const unsigned dyp = (unsigned)(y0 + b - yp);
                        if (!((dxp <= 1u) && (dyp <= 1u))) ++c;
                    }
            }
            if (p == 0) c0 = c; else c1 = c;
        }

        // ---- Block exclusive scan over the 256 step-counts ----
        const int s0 = warpInclScan(c0);
        const int s1 = warpInclScan(c1);
        if (lane == 31) { wsum[w] = s0; wsum[4 + w] = s1; }
        __syncthreads();
        int b0 = 0, b1 = 0, tot0 = 0, tot1 = 0;
        #pragma unroll
        for (int k = 0; k < 4; ++k) {
            if (k < w) { b0 += wsum[k]; b1 += wsum[4 + k]; }
            tot0 += wsum[k];
            tot1 += wsum[4 + k];
        }
        const int off0 = b0 + s0 - c0;
        const int off1 = tot0 + b1 + s1 - c1;
        const int E    = tot0 + tot1;
        const int Epad = (E + 31) & ~31;

        // ---- Phase 2: recompute and write compacted entries ----
        #pragma unroll
        for (int p = 0; p < 2; ++p) {
            const int s = tid + p * 128;
            if (s < cnt) {
                int pos = (p == 0) ? off0 : off1;
                int x0, y0; float wx0, wx1, wy0, wy1;
                patchOf(i0 + s, bx, by, rx, ry, x0, y0, wx0, wx1, wy0, wy1);
                int xp = 0x40000000, yp = 0x40000000;
                if (s > 0) {
                    float d0, d1, d2, d3;
                    patchOf(i0 + s - 1, bx, by, rx, ry, xp, yp, d0, d1, d2, d3);
                }
                int xn = 0x40000000, yn = 0x40000000;
                float wxn0 = 0.f, wxn1 = 0.f, wyn0 = 0.f, wyn1 = 0.f;
                if (s + 1 < cnt) {
                    patchOf(i0 + s + 1, bx, by, rx, ry, xn, yn, wxn0, wxn1, wyn0, wyn1);
                }
                #pragma unroll
                for (int a = 0; a < 2; ++a)
                    #pragma unroll
                    for (int b = 0; b < 2; ++b) {
                        const unsigned dxp = (unsigned)(x0 + a - xp);
                        const unsigned dyp = (unsigned)(y0 + b - yp);
                        if (!((dxp <= 1u) && (dyp <= 1u))) {
                            const float wa = (a == 0) ? wx0 : wx1;
                            const float wb = (b == 0) ? wy0 : wy1;
                            float wgt = wa * wb;
                            const unsigned an = (unsigned)(x0 + a - xn);
                            const unsigned bn = (unsigned)(y0 + b - yn);
                            if ((an <= 1u) && (bn <= 1u)) {
                                const float wan = (an == 0u) ? wxn0 : wxn1;
                                const float wbn = (bn == 0u) ? wyn0 : wyn1;
                                wgt += wan * wbn;
                            }
                            const int xc = min(max(x0 + a, 0), XD - 1);
                            const int yc = min(max(y0 + b, 0), XD - 1);
                            AW[pos] = make_int2((xc * XD + yc) << 9, __float_as_int(wgt));
                            ++pos;
                        }
                    }
            }
        }
        // Zero-weight padding entries up to Epad.
        for (int e = E + tid; e < Epad; e += 128) AW[e] = make_int2(0, 0);
        __syncthreads();

        // ---- Mainloop: per warp 8 entries/trip -> 8 LDG.128 in flight + 32 FFMA ----
        const char* volb = (const char*)vol + (lane << 4);
        float4 S0 = make_float4(0.f, 0.f, 0.f, 0.f);
        float4 S1 = make_float4(0.f, 0.f, 0.f, 0.f);
        for (int e = 8 * w; e < Epad; e += 32) {
            #pragma unroll
            for (int u = 0; u < 8; ++u) {
                const int2  aw = AW[e + u];
                const float4 q = __ldg((const float4*)(volb + aw.x));
                const float wt = __int_as_float(aw.y);
                if (u & 1) {
                    S1.x = fmaf(wt, q.x, S1.x); S1.y = fmaf(wt, q.y, S1.y);
                    S1.z = fmaf(wt, q.z, S1.z); S1.w = fmaf(wt, q.w, S1.w);
                } else {
                    S0.x = fmaf(wt, q.x, S0.x); S0.y = fmaf(wt, q.y, S0.y);
                    S0.z = fmaf(wt, q.z, S0.z); S0.w = fmaf(wt, q.w, S0.w);
                }
            }
        }
        Red[w][lane * 4 + 0] = S0.x + S1.x;
        Red[w][lane * 4 + 1] = S0.y + S1.y;
        Red[w][lane * 4 + 2] = S0.z + S1.z;
        Red[w][lane * 4 + 3] = S0.w + S1.w;
        __syncthreads();

        const float acc = Red[0][tid] + Red[1][tid] + Red[2][tid] + Red[3][tid];
        out[((n * XD) + j) * XD + tid] = acc * (float)SCALE_D;
    } else {
        // General path: per-pixel trilinear gather, full depth, plain store.
        const int z = tid;
        const float kc = (float)z - 63.5f;
        const float bx = fmaf(kc, vx, fmaf(jc, ux, dx)) + 63.5f;
        const float by = fmaf(kc, vy, fmaf(jc, uy, dy)) + 63.5f;
        const float bz = fmaf(kc, vz, fmaf(jc, uz, dz)) + 63.5f;

        float tlo = -3.0e38f, thi = 3.0e38f;
        bool empty = false;
        slab_axis(rx, bx, tlo, thi, empty);
        slab_axis(ry, by, tlo, thi, empty);
        slab_axis(rz, bz, tlo, thi, empty);

        int i0 = 0, i1 = -1;
        if (!empty && thi >= tlo) {
            i0 = max(0, (int)ceilf((tlo - t0) / dt) - 1);
            i1 = min(NDEPTH - 1, (int)floorf((thi - t0) / dt) + 1);
        }

        float sum = 0.0f;
        for (int i = i0; i <= i1; ++i) {
            const float t  = fmaf((float)i, dt, t0);
            const float px = fmaf(t, rx, bx);
            const float py = fmaf(t, ry, by);
            const float pz = fmaf(t, rz, bz);

            const float x0f = floorf(px);
            const float y0f = floorf(py);
            const float z0f = floorf(pz);
            const float fx = px - x0f;
            const float fy = py - y0f;
            const float fz = pz - z0f;
            const int x0 = (int)x0f;
            const int y0 = (int)y0f;
            const int z0 = (int)z0f;

            const int a = x0 * (XD * XD) + y0 * XD + z0;

            const bool xv0 = ((unsigned)x0 < (unsigned)XD);
            const bool xv1 = ((unsigned)(x0 + 1) < (unsigned)XD);
            const bool yv0 = ((unsigned)y0 < (unsigned)XD);
            const bool yv1 = ((unsigned)(y0 + 1) < (unsigned)XD);
            const bool zv0 = ((unsigned)z0 < (unsigned)XD);
            const bool zv1 = ((unsigned)(z0 + 1) < (unsigned)XD);

            const float v000 = (xv0 & yv0 & zv0) ? __ldg(vol + a)                    : 0.0f;
            const float v001 = (xv0 & yv0 & zv1) ? __ldg(vol + a + 1)                : 0.0f;
            const float v010 = (xv0 & yv1 & zv0) ? __ldg(vol + a + XD)               : 0.0f;
            const float v011 = (xv0 & yv1 & zv1) ? __ldg(vol + a + XD + 1)           : 0.0f;
            const float v100 = (xv1 & yv0 & zv0) ? __ldg(vol + a + XD * XD)          : 0.0f;
            const float v101 = (xv1 & yv0 & zv1) ? __ldg(vol + a + XD * XD + 1)      : 0.0f;
            const float v110 = (xv1 & yv1 & zv0) ? __ldg(vol + a + XD * XD + XD)     : 0.0f;
            const float v111 = (xv1 & yv1 & zv1) ? __ldg(vol + a + XD * XD + XD + 1) : 0.0f;

            const float c00 = fmaf(fz, v001 - v000, v000);
            const float c01 = fmaf(fz, v011 - v010, v010);
            const float c10 = fmaf(fz, v101 - v100, v100);
            const float c11 = fmaf(fz, v111 - v110, v110);
            const float c0  = fmaf(fy, c01 - c00, c00);
            const float c1  = fmaf(fy, c11 - c10, c10);
            sum += fmaf(fx, c1 - c0, c0);
        }
        out[((n * XD) + j) * XD + z] = sum * (float)SCALE_D;
    }
}

extern "C" void kernel_launch(void* const* d_in, const int* in_sizes, int n_in,
                              void* d_out, int out_size) {
    const float* vol = (const float*)d_in[0];
    const float* vec = (const float*)d_in[1];
    float* out = (float*)d_out;

    const int N = in_sizes[1] / 12;
    dim3 grid(XD, N);
    dim3 block(128);
    projector_kernel<<<grid, block>>>(vol, vec, out);
}